// round 4
// baseline (speedup 1.0000x reference)
#include <cuda_runtime.h>

#define NMAX   100000
#define EMAX   1600000
#define DIN    64
#define DHID   64
#define DOUT   32

// ---------------- scratch (no allocations allowed) ----------------
__device__ int   g_is64;             // 1 if edge_index is int64, 0 if int32
__device__ int   g_deg[NMAX];
__device__ int   g_off[NMAX];
__device__ int   g_cur[NMAX];
__device__ int   g_csr[EMAX];
__device__ __align__(16) float g_p1[NMAX * DHID];   // x @ W1l
__device__ __align__(16) float g_q1[NMAX * DHID];   // x @ W1r + b1
__device__ __align__(16) float g_h [NMAX * DHID];   // relu(agg(p1) + q1)
__device__ __align__(16) float g_p2[NMAX * DOUT];   // h @ W2l
__device__ __align__(16) float g_q2[NMAX * DOUT];   // h @ W2r + b2

// ---------------- detect dtype + zero degrees (fused) ----------------
// int64 little-endian with values < 1e5 -> every odd int32 word is 0.
__global__ void k_detect_zero(const int* __restrict__ ei, int* deg, int n) {
    int i = blockIdx.x * blockDim.x + threadIdx.x;
    if (i < n) deg[i] = 0;
    if (i == 0) {
        int orv = 0;
        #pragma unroll
        for (int k = 0; k < 64; k++) orv |= ei[2 * k + 1];
        g_is64 = (orv == 0) ? 1 : 0;
    }
}

__global__ void k_count(const int* __restrict__ ei, int* deg, int E) {
    int e = blockIdx.x * blockDim.x + threadIdx.x;
    if (e < E) {
        long long m = g_is64 + 1;
        int d = ei[((long long)E + e) * m];
        atomicAdd(&deg[d], 1);
    }
}

// ---------------- single-kernel exclusive scan (1 block, chunked) ----------------
__global__ __launch_bounds__(1024) void k_scan_one(
    const int* __restrict__ deg, int* off, int* cur, int n)
{
    __shared__ int wsum[32];
    int tid = threadIdx.x, lane = tid & 31, wid = tid >> 5;
    int carry = 0;
    int nchunks = (n + 4095) / 4096;
    for (int c = 0; c < nchunks; c++) {
        int base = c * 4096 + tid * 4;
        int4 v4 = make_int4(0, 0, 0, 0);
        if (base + 3 < n) v4 = *reinterpret_cast<const int4*>(deg + base);
        else {
            if (base     < n) v4.x = deg[base];
            if (base + 1 < n) v4.y = deg[base + 1];
            if (base + 2 < n) v4.z = deg[base + 2];
        }
        int s0 = v4.x, s1 = s0 + v4.y, s2 = s1 + v4.z, s3 = s2 + v4.w;
        int v = s3;
        #pragma unroll
        for (int d = 1; d < 32; d <<= 1) {
            int t = __shfl_up_sync(0xffffffffu, v, d);
            if (lane >= d) v += t;
        }
        if (lane == 31) wsum[wid] = v;
        __syncthreads();
        if (wid == 0) {
            int w = wsum[lane];
            #pragma unroll
            for (int d = 1; d < 32; d <<= 1) {
                int t = __shfl_up_sync(0xffffffffu, w, d);
                if (lane >= d) w += t;
            }
            wsum[lane] = w;
        }
        __syncthreads();
        int pre = carry + (wid > 0 ? wsum[wid - 1] : 0) + (v - s3);
        if (base     < n) { off[base]     = pre;      cur[base]     = pre;      }
        if (base + 1 < n) { off[base + 1] = pre + s0; cur[base + 1] = pre + s0; }
        if (base + 2 < n) { off[base + 2] = pre + s1; cur[base + 2] = pre + s1; }
        if (base + 3 < n) { off[base + 3] = pre + s2; cur[base + 3] = pre + s2; }
        int total = wsum[31];
        __syncthreads();
        carry += total;
    }
}

__global__ void k_scatter(const int* __restrict__ ei, int* cur, int* csr, int E) {
    int e = blockIdx.x * blockDim.x + threadIdx.x;
    if (e < E) {
        long long m = g_is64 + 1;
        int s = ei[(long long)e * m];
        int d = ei[((long long)E + e) * m];
        int pos = atomicAdd(&cur[d], 1);
        csr[pos] = s;
    }
}

// ---------------- register-tiled dual GEMM ----------------
// Computes p = x@Wl, q = x@Wr + b for x [n,64], Wl/Wr [64,DO] row-major.
// Concat cols: NC = 2*DO. Block tile: MT nodes x NC cols, 256 threads,
// per-thread 4x4 register tile. MT = 1024/ (NC/4) * ... chosen per instance.
template<int MT, int DO>
__global__ __launch_bounds__(256) void k_gemm_dual(
    const float* __restrict__ x, const float* __restrict__ Wl,
    const float* __restrict__ Wr, const float* __restrict__ b,
    float* __restrict__ p, float* __restrict__ q, int n)
{
    constexpr int NC = 2 * DO;
    constexpr int TN = NC / 4;           // thread cols groups
    static_assert(TN * (MT / 4) == 256, "bad tile");
    __shared__ float sXT[64][MT + 4];    // transposed x tile, padded
    __shared__ float sW [64][NC];        // [Wl | Wr], k-major

    int t = threadIdx.x;
    int nodeBase = blockIdx.x * MT;

    // load weights (one-time): sW[k][c]
    for (int i = t; i < 64 * NC; i += 256) {
        int k = i / NC, c = i % NC;
        sW[k][c] = (c < DO) ? Wl[k * DO + c] : Wr[k * DO + (c - DO)];
    }
    // load x tile transposed: sXT[k][m] = x[nodeBase+m][k]
    constexpr int F4 = MT * 16 / 256;    // float4 loads per thread
    #pragma unroll
    for (int i = 0; i < F4; i++) {
        int flat = t + i * 256;          // float4 index over [MT][16]
        int nd = flat >> 4, k4 = (flat & 15) * 4;
        int node = nodeBase + nd;
        float4 v = make_float4(0.f, 0.f, 0.f, 0.f);
        if (node < n) v = *reinterpret_cast<const float4*>(x + (size_t)node * 64 + k4);
        sXT[k4 + 0][nd] = v.x;
        sXT[k4 + 1][nd] = v.y;
        sXT[k4 + 2][nd] = v.z;
        sXT[k4 + 3][nd] = v.w;
    }
    __syncthreads();

    int tn = t % TN;                     // col group (4 cols)
    int tm = t / TN;                     // row group (4 rows)
    float acc[4][4];
    #pragma unroll
    for (int r = 0; r < 4; r++)
        #pragma unroll
        for (int c = 0; c < 4; c++) acc[r][c] = 0.0f;

    #pragma unroll 8
    for (int k = 0; k < 64; k++) {
        float4 bv = *reinterpret_cast<const float4*>(&sW[k][tn * 4]);
        float4 av = *reinterpret_cast<const float4*>(&sXT[k][tm * 4]);
        float a[4] = {av.x, av.y, av.z, av.w};
        float bb[4] = {bv.x, bv.y, bv.z, bv.w};
        #pragma unroll
        for (int r = 0; r < 4; r++)
            #pragma unroll
            for (int c = 0; c < 4; c++)
                acc[r][c] = fmaf(a[r], bb[c], acc[r][c]);
    }

    int cbase = tn * 4;
    bool isQ = (cbase >= DO);
    int col = isQ ? (cbase - DO) : cbase;
    float4 bias = make_float4(0.f, 0.f, 0.f, 0.f);
    if (isQ) bias = *reinterpret_cast<const float4*>(b + col);
    float* dst = isQ ? q : p;

    #pragma unroll
    for (int r = 0; r < 4; r++) {
        int node = nodeBase + tm * 4 + r;
        if (node < n) {
            float4 o;
            o.x = acc[r][0] + bias.x;
            o.y = acc[r][1] + bias.y;
            o.z = acc[r][2] + bias.z;
            o.w = acc[r][3] + bias.w;
            *reinterpret_cast<float4*>(dst + (size_t)node * DO + col) = o;
        }
    }
}

// ---------------- aggregation: one warp per node, 8-wide edge pipelining ----------------
__global__ __launch_bounds__(256) void k_agg64_relu(
    const float* __restrict__ p, const float* __restrict__ q,
    const int* __restrict__ off, const int* __restrict__ deg,
    const int* __restrict__ csr, float* __restrict__ h, int n)
{
    int warp = (blockIdx.x * blockDim.x + threadIdx.x) >> 5;
    int lane = threadIdx.x & 31;
    if (warp >= n) return;
    int o = off[warp];
    int d = deg[warp];
    float ax = 0.0f, ay = 0.0f;
    int e = 0;
    for (; e + 8 <= d; e += 8) {
        int s0 = __ldg(&csr[o + e + 0]);
        int s1 = __ldg(&csr[o + e + 1]);
        int s2 = __ldg(&csr[o + e + 2]);
        int s3 = __ldg(&csr[o + e + 3]);
        int s4 = __ldg(&csr[o + e + 4]);
        int s5 = __ldg(&csr[o + e + 5]);
        int s6 = __ldg(&csr[o + e + 6]);
        int s7 = __ldg(&csr[o + e + 7]);
        float2 v0 = __ldg((const float2*)(p + (long long)s0 * 64 + lane * 2));
        float2 v1 = __ldg((const float2*)(p + (long long)s1 * 64 + lane * 2));
        float2 v2 = __ldg((const float2*)(p + (long long)s2 * 64 + lane * 2));
        float2 v3 = __ldg((const float2*)(p + (long long)s3 * 64 + lane * 2));
        float2 v4 = __ldg((const float2*)(p + (long long)s4 * 64 + lane * 2));
        float2 v5 = __ldg((const float2*)(p + (long long)s5 * 64 + lane * 2));
        float2 v6 = __ldg((const float2*)(p + (long long)s6 * 64 + lane * 2));
        float2 v7 = __ldg((const float2*)(p + (long long)s7 * 64 + lane * 2));
        ax += (v0.x + v1.x) + (v2.x + v3.x) + ((v4.x + v5.x) + (v6.x + v7.x));
        ay += (v0.y + v1.y) + (v2.y + v3.y) + ((v4.y + v5.y) + (v6.y + v7.y));
    }
    for (; e + 2 <= d; e += 2) {
        int s0 = __ldg(&csr[o + e + 0]);
        int s1 = __ldg(&csr[o + e + 1]);
        float2 v0 = __ldg((const float2*)(p + (long long)s0 * 64 + lane * 2));
        float2 v1 = __ldg((const float2*)(p + (long long)s1 * 64 + lane * 2));
        ax += v0.x + v1.x;
        ay += v0.y + v1.y;
    }
    if (e < d) {
        int s0 = __ldg(&csr[o + e]);
        float2 v0 = __ldg((const float2*)(p + (long long)s0 * 64 + lane * 2));
        ax += v0.x; ay += v0.y;
    }
    float inv = 1.0f / (float)max(d, 1);
    float2 qq = __ldg((const float2*)(q + (long long)warp * 64 + lane * 2));
    float2 out;
    out.x = fmaxf(fmaf(ax, inv, qq.x), 0.0f);
    out.y = fmaxf(fmaf(ay, inv, qq.y), 0.0f);
    *reinterpret_cast<float2*>(h + (long long)warp * 64 + lane * 2) = out;
}

__global__ __launch_bounds__(256) void k_agg32(
    const float* __restrict__ p, const float* __restrict__ q,
    const int* __restrict__ off, const int* __restrict__ deg,
    const int* __restrict__ csr, float* __restrict__ out, int n)
{
    int warp = (blockIdx.x * blockDim.x + threadIdx.x) >> 5;
    int lane = threadIdx.x & 31;
    if (warp >= n) return;
    int o = off[warp];
    int d = deg[warp];
    float a = 0.0f;
    int e = 0;
    for (; e + 8 <= d; e += 8) {
        int s0 = __ldg(&csr[o + e + 0]);
        int s1 = __ldg(&csr[o + e + 1]);
        int s2 = __ldg(&csr[o + e + 2]);
        int s3 = __ldg(&csr[o + e + 3]);
        int s4 = __ldg(&csr[o + e + 4]);
        int s5 = __ldg(&csr[o + e + 5]);
        int s6 = __ldg(&csr[o + e + 6]);
        int s7 = __ldg(&csr[o + e + 7]);
        float v0 = __ldg(p + (long long)s0 * 32 + lane);
        float v1 = __ldg(p + (long long)s1 * 32 + lane);
        float v2 = __ldg(p + (long long)s2 * 32 + lane);
        float v3 = __ldg(p + (long long)s3 * 32 + lane);
        float v4 = __ldg(p + (long long)s4 * 32 + lane);
        float v5 = __ldg(p + (long long)s5 * 32 + lane);
        float v6 = __ldg(p + (long long)s6 * 32 + lane);
        float v7 = __ldg(p + (long long)s7 * 32 + lane);
        a += (v0 + v1) + (v2 + v3) + ((v4 + v5) + (v6 + v7));
    }
    for (; e + 2 <= d; e += 2) {
        int s0 = __ldg(&csr[o + e + 0]);
        int s1 = __ldg(&csr[o + e + 1]);
        a += __ldg(p + (long long)s0 * 32 + lane) + __ldg(p + (long long)s1 * 32 + lane);
    }
    if (e < d) {
        int s0 = __ldg(&csr[o + e]);
        a += __ldg(p + (long long)s0 * 32 + lane);
    }
    float inv = 1.0f / (float)max(d, 1);
    out[(long long)warp * 32 + lane] = fmaf(a, inv, q[(long long)warp * 32 + lane]);
}

// ---------------- launcher ----------------
extern "C" void kernel_launch(void* const* d_in, const int* in_sizes, int n_in,
                              void* d_out, int out_size)
{
    const float* x   = (const float*)d_in[0];
    const int*   ei  = (const int*)d_in[1];     // int32 view; stride from g_is64
    const float* W1l = (const float*)d_in[2];
    const float* b1l = (const float*)d_in[3];
    const float* W1r = (const float*)d_in[4];
    const float* W2l = (const float*)d_in[5];
    const float* b2l = (const float*)d_in[6];
    const float* W2r = (const float*)d_in[7];
    float* out = (float*)d_out;

    int n = in_sizes[0] / DIN;     // 100000
    int E = in_sizes[1] / 2;       // 1600000

    int* deg = g_deg;  int* off = g_off;  int* cur = g_cur;  int* csr = g_csr;
    float* p1 = g_p1;  float* q1 = g_q1;  float* h = g_h;
    float* p2 = g_p2;  float* q2 = g_q2;

    // slot 1..3: CSR front
    k_detect_zero<<<(n + 255) / 256, 256>>>(ei, deg, n);
    k_count<<<(E + 255) / 256, 256>>>(ei, deg, E);
    k_scan_one<<<1, 1024>>>(deg, off, cur, n);
    // slot 4: scatter -- profiled by ncu this round
    k_scatter<<<(E + 255) / 256, 256>>>(ei, cur, csr, E);

    // layer 1: h = relu( mean-agg(x@W1l) + x@W1r + b1 )
    // gemm64: MT=32 nodes, DO=64 (NC=128, TN=32)
    k_gemm_dual<32, 64><<<(n + 31) / 32, 256>>>(x, W1l, W1r, b1l, p1, q1, n);
    k_agg64_relu<<<(n + 7) / 8, 256>>>(p1, q1, off, deg, csr, h, n);

    // layer 2: out = mean-agg(h@W2l) + h@W2r + b2
    // gemm32: MT=64 nodes, DO=32 (NC=64, TN=16)
    k_gemm_dual<64, 32><<<(n + 63) / 64, 256>>>(h, W2l, W2r, b2l, p2, q2, n);
    k_agg32<<<(n + 7) / 8, 256>>>(p2, q2, off, deg, csr, out, n);
}